// round 16
// baseline (speedup 1.0000x reference)
#include <cuda_runtime.h>
#include <cuda_bf16.h>
#include <mma.h>
#include <cstdint>

using namespace nvcuda;

#if defined(__CUDA_ARCH_SPECIFIC__) || defined(__CUDA_ARCH_FEAT_SM103_ALL) || defined(__CUDA_ARCH_FEAT_SM100_ALL)
#define HAS_TCGEN05 1
#else
#define HAS_TCGEN05 0
#endif

// ---------------------------------------------------------------------------
#define BATCH   1024
#define NNEG    128
#define ED      600
#define VFS_D   12288
#define OBJ_VD  4096

#define KP18    1920            // 1800 padded to 128-multiple
#define NP600   768
#define NP1800  2048

// ---------------------------------------------------------------------------
__device__ __nv_bfloat16 g_Rv [BATCH * VFS_D];
__device__ __nv_bfloat16 g_Wh1[2048 * 4096];
__device__ __nv_bfloat16 g_We1[NP600 * 2048];
__device__ __nv_bfloat16 g_Wh2[4096 * 12288];
__device__ __nv_bfloat16 g_We2[NP600 * 4096];
__device__ __nv_bfloat16 g_Wh [NP1800 * KP18];
__device__ __nv_bfloat16 g_We [NP600 * KP18];
__device__ __nv_bfloat16 g_H1 [2048 * 2048];
__device__ __nv_bfloat16 g_H2 [1024 * 4096];
__device__ __nv_bfloat16 g_Z  [1024 * KP18];
__device__ __nv_bfloat16 g_H  [1024 * KP18];
__device__ float         g_emb[1024 * ED];

// ---------------------------------------------------------------------------
__device__ __forceinline__ uint32_t sptr(const void* p) {
    return (uint32_t)__cvta_generic_to_shared(p);
}
__device__ __forceinline__ void cp16(uint32_t s, const void* g) {
    asm volatile("cp.async.cg.shared.global [%0], [%1], 16;" :: "r"(s), "l"(g));
}
__device__ __forceinline__ void cp_commit() {
    asm volatile("cp.async.commit_group;");
}
template<int N> __device__ __forceinline__ void cp_wait() {
    asm volatile("cp.async.wait_group %0;" :: "n"(N));
}

struct GD {
    const __nv_bfloat16 *A, *A2;   // A rows < asplit come from A, else A2
    const __nv_bfloat16 *W;
    const float *bias;
    __nv_bfloat16 *out1, *out2;
    float *outF;
    int lda, ldw, N, K, ldc, split, relu, nbx, asplit;
};

#if HAS_TCGEN05
__device__ __forceinline__ uint32_t elect1() {
    uint32_t r;
    asm volatile("{\n\t.reg .pred p;\n\telect.sync _|p, 0xFFFFFFFF;\n\t"
                 "selp.b32 %0, 1, 0, p;\n\t}" : "=r"(r));
    return r;
}

#define TCGEN05_ALLOC(saddr, ncols) \
    asm volatile("tcgen05.alloc.cta_group::1.sync.aligned.shared::cta.b32 [%0], %1;" \
                 :: "r"((uint32_t)(saddr)), "r"((uint32_t)(ncols)) : "memory")
#define TCGEN05_DEALLOC(tmem, ncols) \
    asm volatile("tcgen05.dealloc.cta_group::1.sync.aligned.b32 %0, %1;" \
                 :: "r"(tmem), "r"((uint32_t)(ncols)))
#define TCGEN05_RELINQUISH() \
    asm volatile("tcgen05.relinquish_alloc_permit.cta_group::1.sync.aligned;")
#define TCGEN05_COMMIT(mbar) \
    asm volatile("tcgen05.commit.cta_group::1.mbarrier::arrive::one.shared::cluster.b64 [%0];" \
                 :: "r"((uint32_t)(mbar)) : "memory")
#define TCGEN05_FENCE_AFTER() \
    asm volatile("tcgen05.fence::after_thread_sync;" ::: "memory")
#define TCGEN05_FENCE_BEFORE() \
    asm volatile("tcgen05.fence::before_thread_sync;" ::: "memory")
#define TCGEN05_WAIT_LD() \
    asm volatile("tcgen05.wait::ld.sync.aligned;" ::: "memory")
#define FENCE_PROXY_ASYNC() \
    asm volatile("fence.proxy.async.shared::cta;" ::: "memory")
#define MBARRIER_INIT(mbar, cnt) \
    asm volatile("mbarrier.init.shared.b64 [%0], %1;" \
                 :: "r"((uint32_t)(mbar)), "r"((uint32_t)(cnt)) : "memory")

#define MBARRIER_WAIT_PARITY(mbar_smem_addr, phase_parity) do { \
    uint32_t _mbar = (uint32_t)(mbar_smem_addr); \
    uint32_t _parity = (uint32_t)(phase_parity); \
    uint32_t _done; \
    asm volatile( \
        "{\n\t.reg .pred p;\n\t" \
        "mbarrier.try_wait.parity.acquire.cta.shared::cta.b64 p, [%1], %2;\n\t" \
        "selp.b32 %0, 1, 0, p;\n\t}" \
        : "=r"(_done) : "r"(_mbar), "r"(_parity) : "memory"); \
    if (!_done) { \
        asm volatile( \
            "{\n\t.reg .pred P1;\n\t" \
            "WAIT_LOOP_%=:\n\t" \
            "mbarrier.try_wait.parity.acquire.cta.shared::cta.b64 P1, [%0], %1, 0x989680;\n\t" \
            "@P1 bra.uni WAIT_DONE_%=;\n\t" \
            "bra.uni WAIT_LOOP_%=;\n\t" \
            "WAIT_DONE_%=:\n\t}" \
            :: "r"(_mbar), "r"(_parity) : "memory"); \
    } \
} while(0)

#define TCGEN05_LD_32X32B_X32(r, tmem_addr) \
    asm volatile( \
        "tcgen05.ld.sync.aligned.32x32b.x32.b32 " \
        "{%0, %1, %2, %3, %4, %5, %6, %7, " \
        " %8, %9, %10, %11, %12, %13, %14, %15, " \
        " %16, %17, %18, %19, %20, %21, %22, %23, " \
        " %24, %25, %26, %27, %28, %29, %30, %31}, [%32];" \
        : "=r"((r)[0]),  "=r"((r)[1]),  "=r"((r)[2]),  "=r"((r)[3]), \
          "=r"((r)[4]),  "=r"((r)[5]),  "=r"((r)[6]),  "=r"((r)[7]), \
          "=r"((r)[8]),  "=r"((r)[9]),  "=r"((r)[10]), "=r"((r)[11]), \
          "=r"((r)[12]), "=r"((r)[13]), "=r"((r)[14]), "=r"((r)[15]), \
          "=r"((r)[16]), "=r"((r)[17]), "=r"((r)[18]), "=r"((r)[19]), \
          "=r"((r)[20]), "=r"((r)[21]), "=r"((r)[22]), "=r"((r)[23]), \
          "=r"((r)[24]), "=r"((r)[25]), "=r"((r)[26]), "=r"((r)[27]), \
          "=r"((r)[28]), "=r"((r)[29]), "=r"((r)[30]), "=r"((r)[31]) \
        : "r"(tmem_addr))

// SW128 K-major smem descriptor
static constexpr uint64_t DESC_BASE =
    (uint64_t(2) << 61) | (uint64_t(1) << 46) | (uint64_t(64) << 32) | (uint64_t(1) << 16);

// idescs: kind::f16, dtype=F32, atype=btype=BF16, M=128
#define IDESC128 ((1u << 4) | (1u << 7) | (1u << 10) | ((128u / 8) << 17) | ((128u / 16) << 24))
#define IDESC256 ((1u << 4) | (1u << 7) | (1u << 10) | ((256u / 8) << 17) | ((128u / 16) << 24))

__device__ __forceinline__ void mma_bf16_ss(uint32_t d, uint64_t ad, uint64_t bd,
                                            uint32_t idesc, uint32_t enable) {
    asm volatile(
        "{\n\t.reg .pred p;\n\tsetp.ne.u32 p, %5, 0;\n\t"
        "tcgen05.mma.cta_group::1.kind::f16 [%0], %1, %2, %3, {%4,%4,%4,%4}, p;\n\t}"
        :: "r"(d), "l"(ad), "l"(bd), "r"(idesc), "r"(0u), "r"(enable) : "memory");
}
#endif  // HAS_TCGEN05

// ---------------------------------------------------------------------------
// Converts
// ---------------------------------------------------------------------------
static inline int cdiv(int a, int b) { return (a + b - 1) / b; }

__global__ void cvt_f32_b16(const float* __restrict__ src, __nv_bfloat16* __restrict__ dst,
                            int n, int do_relu) {
    int i = (blockIdx.x * blockDim.x + threadIdx.x) * 4;
    if (i >= n) return;
    float4 v = *reinterpret_cast<const float4*>(src + i);
    if (do_relu) {
        v.x = fmaxf(v.x, 0.f); v.y = fmaxf(v.y, 0.f);
        v.z = fmaxf(v.z, 0.f); v.w = fmaxf(v.w, 0.f);
    }
    *reinterpret_cast<__nv_bfloat162*>(dst + i)     = __floats2bfloat162_rn(v.x, v.y);
    *reinterpret_cast<__nv_bfloat162*>(dst + i + 2) = __floats2bfloat162_rn(v.z, v.w);
}

__global__ void cvt2d_f32_b16(const float* __restrict__ src, __nv_bfloat16* __restrict__ dst,
                              int R, int Ks, int Kd) {
    int i = (blockIdx.x * blockDim.x + threadIdx.x) * 4;
    if (i >= R * Ks) return;
    int r = i / Ks, c = i - r * Ks;
    float4 v = *reinterpret_cast<const float4*>(src + i);
    __nv_bfloat16* d = dst + (size_t)r * Kd + c;
    *reinterpret_cast<__nv_bfloat162*>(d)     = __floats2bfloat162_rn(v.x, v.y);
    *reinterpret_cast<__nv_bfloat162*>(d + 2) = __floats2bfloat162_rn(v.z, v.w);
}

// ---------------------------------------------------------------------------
// Shared wmma fallback tile (plain sm_103 pass only; not selected on 103a)
// ---------------------------------------------------------------------------
#if !HAS_TCGEN05
#define LDSB 72
__device__ void wmma_tile128(const GD& d, int m0, int n0, char* smraw,
                             int tid, int warp, int lane) {
    __nv_bfloat16* Asm = reinterpret_cast<__nv_bfloat16*>(smraw);
    __nv_bfloat16* Bsm = Asm + 2 * 128 * LDSB;
    const int wm = warp >> 2;
    const int wn = warp & 3;

    wmma::fragment<wmma::accumulator, 16, 16, 16, float> acc[4][2];
#pragma unroll
    for (int i = 0; i < 4; i++)
#pragma unroll
        for (int j = 0; j < 2; j++)
            wmma::fill_fragment(acc[i][j], 0.0f);

    const int KT = d.K >> 6;
    auto issue = [&](int kt) {
        const int k0 = kt << 6;
        __nv_bfloat16* a = Asm + (kt & 1) * 128 * LDSB;
        __nv_bfloat16* b = Bsm + (kt & 1) * 128 * LDSB;
#pragma unroll
        for (int t = 0; t < 4; t++) {
            int v = tid + t * 256;
            int r = v >> 3;
            int c = (v & 7) << 3;
            int gr = m0 + r;
            const __nv_bfloat16* ap = (gr < d.asplit)
                ? d.A  + (size_t)gr * d.lda
                : d.A2 + (size_t)(gr - d.asplit) * d.lda;
            cp16(sptr(a + r * LDSB + c), ap + k0 + c);
            cp16(sptr(b + r * LDSB + c), d.W + (size_t)(n0 + r) * d.ldw + k0 + c);
        }
        cp_commit();
    };

    issue(0);
    for (int kt = 0; kt < KT; kt++) {
        if (kt + 1 < KT) { issue(kt + 1); cp_wait<1>(); }
        else             { cp_wait<0>(); }
        __syncthreads();
        const __nv_bfloat16* a = Asm + (kt & 1) * 128 * LDSB;
        const __nv_bfloat16* b = Bsm + (kt & 1) * 128 * LDSB;
#pragma unroll
        for (int kk = 0; kk < 64; kk += 16) {
            wmma::fragment<wmma::matrix_a, 16, 16, 16, __nv_bfloat16, wmma::row_major> af[4];
            wmma::fragment<wmma::matrix_b, 16, 16, 16, __nv_bfloat16, wmma::col_major> bf[2];
#pragma unroll
            for (int i = 0; i < 4; i++)
                wmma::load_matrix_sync(af[i], a + (wm * 64 + i * 16) * LDSB + kk, LDSB);
#pragma unroll
            for (int j = 0; j < 2; j++)
                wmma::load_matrix_sync(bf[j], b + (wn * 32 + j * 16) * LDSB + kk, LDSB);
#pragma unroll
            for (int i = 0; i < 4; i++)
#pragma unroll
                for (int j = 0; j < 2; j++)
                    wmma::mma_sync(acc[i][j], af[i], bf[j], acc[i][j]);
        }
        __syncthreads();
    }

    float* st = reinterpret_cast<float*>(smraw) + warp * 256;
#pragma unroll
    for (int i = 0; i < 4; i++) {
#pragma unroll
        for (int j = 0; j < 2; j++) {
            wmma::store_matrix_sync(st, acc[i][j], 16, wmma::mem_row_major);
            __syncwarp();
            int m_base = m0 + wm * 64 + i * 16;
            int n_base = n0 + wn * 32 + j * 16;
#pragma unroll
            for (int e = 0; e < 8; e++) {
                int idx = lane * 8 + e;
                int r = idx >> 4, c = idx & 15;
                int gm = m_base + r;
                int gn = n_base + c;
                if (gn < d.N) {
                    float vv = st[idx] + d.bias[gn];
                    if (d.relu) vv = fmaxf(vv, 0.f);
                    if (d.outF) {
                        d.outF[(size_t)gm * d.ldc + gn] = vv;
                    } else {
                        __nv_bfloat16 hv = __float2bfloat16(vv);
                        if (gm < d.split) d.out1[(size_t)gm * d.ldc + gn] = hv;
                        else              d.out2[(size_t)(gm - d.split) * d.ldc + gn] = hv;
                    }
                }
            }
            __syncwarp();
        }
    }
    __syncthreads();
}
#endif

// ---------------------------------------------------------------------------
// GEMM kernel 1: 128(M) x 128(N) tile, K-chunk 128, 3-stage
// GEMM kernel 2: 128(M) x 256(N) tile, K-chunk 64, 4-stage (split-A input)
// ---------------------------------------------------------------------------
#define STG128_BYTES 65536
#define AB128        32768
#define ASTG256      16384
#define STG256_BYTES 49152
#define GSMEM        200704     // 4096 (align+control) + 196608

__global__ __launch_bounds__(256)
void gemm128(GD d) {
    const int bx = blockIdx.x;
    const int m0 = (bx / d.nbx) * 128;
    const int n0 = (bx % d.nbx) * 128;
    const int tid  = threadIdx.x;
    const int warp = tid >> 5;
    const int lane = tid & 31;

#if HAS_TCGEN05
    extern __shared__ char smraw[];
    const uint32_t sm0   = sptr(smraw);
    const uint32_t mbar0 = sm0 + 8;
    float* biasS = reinterpret_cast<float*>(smraw + 64);
    const uint32_t sA0   = (sm0 + 4095u) & ~4095u;

    const int KT = d.K >> 7;

    if (warp == 0) TCGEN05_ALLOC(sm0, 128);
    if (tid < 3) MBARRIER_INIT(mbar0 + tid * 8, 1);
    if (tid >= 64 && tid < 192) {
        int c = tid - 64;
        biasS[c] = (n0 + c < d.N) ? d.bias[n0 + c] : 0.f;
    }
    __syncthreads();

    uint32_t tmem;
    asm volatile("ld.shared.b32 %0, [%1];" : "=r"(tmem) : "r"(sm0));

    auto issue = [&](int kt, int buf) {
        const uint32_t aS = sA0 + buf * STG128_BYTES;
        const uint32_t bS = aS + AB128;
        const int k0 = kt << 7;
#pragma unroll
        for (int i = 0; i < 8; i++) {
            int v = tid + i * 256;
            int r = v >> 4;
            int c = v & 15;
            uint32_t off = ((uint32_t)(r >> 3) << 10) + ((uint32_t)(c >> 3) << 14)
                         + ((uint32_t)(r & 7) << 7) + ((uint32_t)(c & 7) << 4);
            off ^= (off >> 3) & 0x70u;
            cp16(aS + off, d.A + (size_t)(m0 + r) * d.lda + k0 + (c << 3));
            cp16(bS + off, d.W + (size_t)(n0 + r) * d.ldw + k0 + (c << 3));
        }
        cp_commit();
    };

    issue(0, 0); issue(1, 1); issue(2, 2);

    for (int kt = 0; kt < KT; kt++) {
        const int buf = kt % 3;
        const int rem = KT - kt - 1;
        if (rem >= 2)      cp_wait<2>();
        else if (rem == 1) cp_wait<1>();
        else               cp_wait<0>();
        FENCE_PROXY_ASYNC();
        __syncthreads();

        if (warp == 0 && elect1()) {
            const uint32_t aS = sA0 + buf * STG128_BYTES;
            const uint64_t ad = DESC_BASE | ((aS >> 4) & 0x3FFF);
            const uint64_t bd = DESC_BASE | (((aS + AB128) >> 4) & 0x3FFF);
#pragma unroll
            for (int j = 0; j < 8; j++) {
                uint64_t off = (j < 4) ? (uint64_t)(2 * j) : (uint64_t)(1024 + 2 * (j - 4));
                mma_bf16_ss(tmem, ad + off, bd + off, IDESC128,
                            (kt > 0 || j > 0) ? 1u : 0u);
            }
            TCGEN05_COMMIT(mbar0 + buf * 8);
        }

        if (kt + 3 < KT) {
            MBARRIER_WAIT_PARITY(mbar0 + buf * 8, (uint32_t)((kt / 3) & 1));
            issue(kt + 3, buf);
        }
    }

    {
        const int lb = (KT - 1) % 3;
        MBARRIER_WAIT_PARITY(mbar0 + lb * 8, (uint32_t)(((KT - 1) / 3) & 1));
    }
    TCGEN05_FENCE_AFTER();

    if (warp < 4) {
        const int gm = m0 + warp * 32 + lane;
#pragma unroll
        for (int ch = 0; ch < 4; ch++) {
            uint32_t r[32];
            TCGEN05_LD_32X32B_X32(r, tmem + ch * 32);
            TCGEN05_WAIT_LD();
            const int nb = n0 + ch * 32;
            if (d.outF) {
                float* po = d.outF + (size_t)gm * d.ldc;
#pragma unroll
                for (int c = 0; c < 32; c++) {
                    int gn = nb + c;
                    if (gn < d.N) {
                        float v = __uint_as_float(r[c]) + biasS[ch * 32 + c];
                        if (d.relu) v = fmaxf(v, 0.f);
                        po[gn] = v;
                    }
                }
            } else {
                __nv_bfloat16* po = (gm < d.split) ? d.out1 + (size_t)gm * d.ldc
                                                   : d.out2 + (size_t)(gm - d.split) * d.ldc;
#pragma unroll
                for (int p = 0; p < 16; p++) {
                    int gn = nb + 2 * p;
                    if (gn < d.N) {
                        float v0 = __uint_as_float(r[2 * p])     + biasS[ch * 32 + 2 * p];
                        float v1 = __uint_as_float(r[2 * p + 1]) + biasS[ch * 32 + 2 * p + 1];
                        if (d.relu) { v0 = fmaxf(v0, 0.f); v1 = fmaxf(v1, 0.f); }
                        uint32_t pk;
                        asm("cvt.rn.bf16x2.f32 %0, %1, %2;" : "=r"(pk) : "f"(v1), "f"(v0));
                        *reinterpret_cast<uint32_t*>(po + gn) = pk;
                    }
                }
            }
        }
        TCGEN05_FENCE_BEFORE();
    }
    __syncthreads();
    if (warp == 0) {
        TCGEN05_RELINQUISH();
        TCGEN05_DEALLOC(tmem, 128);
    }
#else
    extern __shared__ char smraw[];
    wmma_tile128(d, m0, n0, smraw, tid, warp, lane);
#endif
}

__global__ __launch_bounds__(256)
void gemm256(GD d) {
    const int bx = blockIdx.x;
    const int m0 = (bx / d.nbx) * 128;
    const int n0 = (bx % d.nbx) * 256;
    const int tid  = threadIdx.x;
    const int warp = tid >> 5;
    const int lane = tid & 31;

#if HAS_TCGEN05
    extern __shared__ char smraw[];
    const uint32_t sm0   = sptr(smraw);
    const uint32_t mbar0 = sm0 + 8;
    float* biasS = reinterpret_cast<float*>(smraw + 64);
    const uint32_t sA0   = (sm0 + 4095u) & ~4095u;

    const int KT = d.K >> 6;

    if (warp == 0) TCGEN05_ALLOC(sm0, 256);
    if (tid < 4) MBARRIER_INIT(mbar0 + tid * 8, 1);
    biasS[tid] = (n0 + tid < d.N) ? d.bias[n0 + tid] : 0.f;
    __syncthreads();

    uint32_t tmem;
    asm volatile("ld.shared.b32 %0, [%1];" : "=r"(tmem) : "r"(sm0));

    auto issue = [&](int kt, int buf) {
        const uint32_t base = sA0 + buf * STG256_BYTES;
        const int k0 = kt << 6;
#pragma unroll
        for (int i = 0; i < 4; i++) {
            int v = tid + i * 256;
            int r = v >> 3;
            int c = v & 7;
            uint32_t off = ((uint32_t)r << 7) + ((uint32_t)c << 4);
            off ^= (off >> 3) & 0x70u;
            int gr = m0 + r;
            const __nv_bfloat16* ap = (gr < d.asplit)
                ? d.A  + (size_t)gr * d.lda
                : d.A2 + (size_t)(gr - d.asplit) * d.lda;
            cp16(base + off, ap + k0 + (c << 3));
        }
#pragma unroll
        for (int i = 0; i < 8; i++) {
            int v = tid + i * 256;
            int r = v >> 3;
            int c = v & 7;
            uint32_t off = ((uint32_t)r << 7) + ((uint32_t)c << 4);
            off ^= (off >> 3) & 0x70u;
            cp16(base + ASTG256 + off, d.W + (size_t)(n0 + r) * d.ldw + k0 + (c << 3));
        }
        cp_commit();
    };

    issue(0, 0); issue(1, 1); issue(2, 2); issue(3, 3);

    for (int kt = 0; kt < KT; kt++) {
        const int buf = kt & 3;
        const int rem = KT - kt - 1;
        if (rem >= 3)      cp_wait<3>();
        else if (rem == 2) cp_wait<2>();
        else if (rem == 1) cp_wait<1>();
        else               cp_wait<0>();
        FENCE_PROXY_ASYNC();
        __syncthreads();

        if (warp == 0 && elect1()) {
            const uint32_t base = sA0 + buf * STG256_BYTES;
            const uint64_t ad = DESC_BASE | ((base >> 4) & 0x3FFF);
            const uint64_t bd = DESC_BASE | (((base + ASTG256) >> 4) & 0x3FFF);
#pragma unroll
            for (int k = 0; k < 4; k++) {
                mma_bf16_ss(tmem, ad + 2 * k, bd + 2 * k, IDESC256,
                            (kt > 0 || k > 0) ? 1u : 0u);
            }
            TCGEN05_COMMIT(mbar0 + buf * 8);
        }

        if (kt + 4 < KT) {
            MBARRIER_WAIT_PARITY(mbar0 + buf * 8, (uint32_t)((kt >> 2) & 1));
            issue(kt + 4, buf);
        }
    }

    {
        const int lb = (KT - 1) & 3;
        MBARRIER_WAIT_PARITY(mbar0 + lb * 8, (uint32_t)(((KT - 1) >> 2) & 1));
    }
    TCGEN05_FENCE_AFTER();

    {
        const int h  = warp >> 2;
        const int w4 = warp & 3;
        const int gm = m0 + w4 * 32 + lane;
#pragma unroll
        for (int ch = 0; ch < 4; ch++) {
            uint32_t r[32];
            const int colbase = h * 128 + ch * 32;
            TCGEN05_LD_32X32B_X32(r, tmem + colbase);
            TCGEN05_WAIT_LD();
            const int nb = n0 + colbase;
            if (d.outF) {
                float* po = d.outF + (size_t)gm * d.ldc;
#pragma unroll
                for (int c = 0; c < 32; c++) {
                    int gn = nb + c;
                    if (gn < d.N) {
                        float v = __uint_as_float(r[c]) + biasS[colbase + c];
                        if (d.relu) v = fmaxf(v, 0.f);
                        po[gn] = v;
                    }
                }
            } else {
                __nv_bfloat16* po = (gm < d.split) ? d.out1 + (size_t)gm * d.ldc
                                                   : d.out2 + (size_t)(gm - d.split) * d.ldc;
#pragma unroll
                for (int p = 0; p < 16; p++) {
                    int gn = nb + 2 * p;
                    if (gn < d.N) {
                        float v0 = __uint_as_float(r[2 * p])     + biasS[colbase + 2 * p];
                        float v1 = __uint_as_float(r[2 * p + 1]) + biasS[colbase + 2 * p + 1];
                        if (d.relu) { v0 = fmaxf(v0, 0.f); v1 = fmaxf(v1, 0.f); }
                        uint32_t pk;
                        asm("cvt.rn.bf16x2.f32 %0, %1, %2;" : "=r"(pk) : "f"(v1), "f"(v0));
                        *reinterpret_cast<uint32_t*>(po + gn) = pk;
                    }
                }
            }
        }
        TCGEN05_FENCE_BEFORE();
    }
    __syncthreads();
    if (warp == 0) {
        TCGEN05_RELINQUISH();
        TCGEN05_DEALLOC(tmem, 256);
    }
#else
    extern __shared__ char smraw[];
    wmma_tile128(d, m0, n0, smraw, tid, warp, lane);
    wmma_tile128(d, m0, n0 + 128, smraw, tid, warp, lane);
#endif
}

// ---------------------------------------------------------------------------
// Scoring
// ---------------------------------------------------------------------------
__global__ void score_kernel(const float* __restrict__ L,
                             const int* __restrict__ pls,
                             const int* __restrict__ nls,
                             float* __restrict__ out) {
    int b = blockIdx.x;
    __shared__ float es[ED];
    for (int i = threadIdx.x; i < ED; i += blockDim.x) es[i] = g_emb[b * ED + i];
    __syncthreads();

    int warp = threadIdx.x >> 5;
    int lane = threadIdx.x & 31;
    for (int j = warp; j < NNEG + 1; j += 8) {
        int idx = (j == 0) ? pls[b] : nls[b * NNEG + (j - 1)];
        const float* Lr = L + (size_t)idx * ED;
        float s = 0.f;
        for (int c = lane; c < ED; c += 32) {
            float d = fmaxf(Lr[c] - es[c], 0.f);
            s += d * d;
        }
#pragma unroll
        for (int o = 16; o; o >>= 1) s += __shfl_xor_sync(0xffffffffu, s, o);
        if (lane == 0) out[b * (NNEG + 1) + j] = -sqrtf(s);
    }
}

// ---------------------------------------------------------------------------
// Launch: multi-stream fork/join; Wh2 cvt split 1/4 + 3/4 pipelined into
// GEMM C quarters; D gated only on C_rest + We2 (not Wh/We cvts);
// GEMM A reads Rv directly via split-A (pack kernel removed).
// All event records precede their waits in host issue order (capture-safe).
// ---------------------------------------------------------------------------
extern "C" void kernel_launch(void* const* d_in, const int* in_sizes, int n_in,
                              void* d_out, int out_size) {
    const float* vfs  = (const float*)d_in[0];
    const float* L    = (const float*)d_in[1];
    const int*   pls  = (const int*)  d_in[2];
    const int*   nls  = (const int*)  d_in[3];
    const float* W_h1 = (const float*)d_in[4];
    const float* b_h1 = (const float*)d_in[5];
    const float* W_e1 = (const float*)d_in[6];
    const float* b_e1 = (const float*)d_in[7];
    const float* W_h2 = (const float*)d_in[8];
    const float* b_h2 = (const float*)d_in[9];
    const float* W_e2 = (const float*)d_in[10];
    const float* b_e2 = (const float*)d_in[11];
    const float* W_h  = (const float*)d_in[12];
    const float* b_h  = (const float*)d_in[13];
    const float* W_e  = (const float*)d_in[14];
    const float* b_e  = (const float*)d_in[15];
    float* out = (float*)d_out;

    __nv_bfloat16 *pRv, *pWh1, *pWe1, *pWh2, *pWe2, *pWh, *pWe;
    __nv_bfloat16 *pH1, *pH2, *pZ, *pH;
    float *pEmb;
    cudaGetSymbolAddress((void**)&pRv,  g_Rv);
    cudaGetSymbolAddress((void**)&pWh1, g_Wh1);
    cudaGetSymbolAddress((void**)&pWe1, g_We1);
    cudaGetSymbolAddress((void**)&pWh2, g_Wh2);
    cudaGetSymbolAddress((void**)&pWe2, g_We2);
    cudaGetSymbolAddress((void**)&pWh,  g_Wh);
    cudaGetSymbolAddress((void**)&pWe,  g_We);
    cudaGetSymbolAddress((void**)&pH1,  g_H1);
    cudaGetSymbolAddress((void**)&pH2,  g_H2);
    cudaGetSymbolAddress((void**)&pZ,   g_Z);
    cudaGetSymbolAddress((void**)&pH,   g_H);
    cudaGetSymbolAddress((void**)&pEmb, g_emb);

    cudaFuncSetAttribute(gemm128, cudaFuncAttributeMaxDynamicSharedMemorySize, GSMEM);
    cudaFuncSetAttribute(gemm256, cudaFuncAttributeMaxDynamicSharedMemorySize, GSMEM);

    static cudaStream_t s1 = nullptr, s2 = nullptr;
    static cudaEvent_t evFork = nullptr, evRv = nullptr, evB = nullptr,
                       evW = nullptr, evQ0 = nullptr, evD = nullptr;
    if (!s1) {
        cudaStreamCreateWithFlags(&s1, cudaStreamNonBlocking);
        cudaStreamCreateWithFlags(&s2, cudaStreamNonBlocking);
        cudaEventCreateWithFlags(&evFork, cudaEventDisableTiming);
        cudaEventCreateWithFlags(&evRv,   cudaEventDisableTiming);
        cudaEventCreateWithFlags(&evB,    cudaEventDisableTiming);
        cudaEventCreateWithFlags(&evW,    cudaEventDisableTiming);
        cudaEventCreateWithFlags(&evQ0,   cudaEventDisableTiming);
        cudaEventCreateWithFlags(&evD,    cudaEventDisableTiming);
    }
    cudaStream_t s0 = 0;

    const int T = 256;
    const size_t WH2_Q = (size_t)1024 * VFS_D;     // quarter of Wh2 (1024 rows)
    const int BIG = 1 << 30;

    // ---- s0: pad memsets, then fork ----
    cudaMemsetAsync(pWe1 + 600 * 2048, 0, (size_t)(NP600 - 600) * 2048 * 2, s0);
    cudaMemsetAsync(pWe2 + 600 * 4096, 0, (size_t)(NP600 - 600) * 4096 * 2, s0);
    cudaMemsetAsync(pWh,  0, (size_t)NP1800 * KP18 * 2, s0);
    cudaMemsetAsync(pWe,  0, (size_t)NP600 * KP18 * 2, s0);
    cudaMemsetAsync(pZ,   0, (size_t)1024 * KP18 * 2, s0);
    cudaMemsetAsync(pH,   0, (size_t)1024 * KP18 * 2, s0);
    cudaEventRecord(evFork, s0);
    cudaStreamWaitEvent(s1, evFork, 0);
    cudaStreamWaitEvent(s2, evFork, 0);

    // GEMM descriptors
    // A: split-A input — rows<1024 from Rv[:,0:4096], rows>=1024 from Rv[:,8192:]
    GD A_  = { pRv, pRv + (VFS_D - OBJ_VD), pWh1, b_h1, pH1, pH1, nullptr,
               VFS_D, 4096, 2048, 4096, 2048, 2048, 1, 8, 1024 };
    // C quarter (cols 0-1023) and rest (cols 1024-4095)
    GD CQ_ = { pRv, pRv, pWh2, b_h2, pH2, pH2, nullptr,
               VFS_D, VFS_D, 1024, VFS_D, 4096, 1024, 1, 4, BIG };
    GD CR_ = { pRv, pRv, pWh2 + WH2_Q, b_h2 + 1024, pH2 + 1024, pH2 + 1024, nullptr,
               VFS_D, VFS_D, 3072, VFS_D, 4096, 1024, 1, 12, BIG };
    GD B_  = { pH1, pH1, pWe1, b_e1, pZ, pZ + 1200, nullptr,
               2048, 2048, 600, 2048, KP18, 1024, 1, 5, BIG };
    GD D_  = { pH2, pH2, pWe2, b_e2, pZ + 600, pZ + 600, nullptr,
               4096, 4096, 600, 4096, KP18, 1024, 1, 5, BIG };
    GD E_  = { pZ, pZ, pWh, b_h, pH, pH, nullptr,
               KP18, KP18, 1800, KP18, KP18, 1024, 1, 15, BIG };
    GD F_  = { pH, pH, pWe, b_e, nullptr, nullptr, pEmb,
               KP18, KP18, 600, KP18, ED, 1024, 0, 5, BIG };

    // ---- s1 first: cvt Rv, record evRv ----
    cvt_f32_b16<<<cdiv(BATCH * VFS_D / 4, T), T, 0, s1>>>(vfs, pRv, BATCH * VFS_D, 1);
    cudaEventRecord(evRv, s1);

    // ---- s0 (critical path): cvt Wh2 quarter -> wait Rv -> GEMM C_Q ----
    cvt_f32_b16<<<cdiv((int)(WH2_Q / 4), T), T, 0, s0>>>(W_h2, pWh2, (int)WH2_Q, 0);
    cudaEventRecord(evQ0, s0);
    cudaStreamWaitEvent(s0, evRv, 0);
    gemm256<<<8 * 4, 256, GSMEM, s0>>>(CQ_);    // 32 CTAs

    // ---- s2: cvt Wh2 rest (overlaps C_Q) -> GEMM C_rest -> We2 -> evD -> Wh/We ----
    cudaStreamWaitEvent(s2, evQ0, 0);
    cvt_f32_b16<<<cdiv((int)(3 * WH2_Q / 4), T), T, 0, s2>>>(
        W_h2 + WH2_Q, pWh2 + WH2_Q, (int)(3 * WH2_Q), 0);
    cudaStreamWaitEvent(s2, evRv, 0);
    gemm256<<<8 * 12, 256, GSMEM, s2>>>(CR_);   // 96 CTAs, dovetails with C_Q
    cvt_f32_b16<<<cdiv(600 * 4096 / 4, T), T, 0, s2>>>(W_e2, pWe2, 600 * 4096, 0);
    cudaEventRecord(evD, s2);                   // C_rest + We2 done -> D can run
    cvt2d_f32_b16<<<cdiv(1800 * 1800 / 4, T), T, 0, s2>>>(W_h, pWh, 1800, 1800, KP18);
    cvt2d_f32_b16<<<cdiv(600 * 1800 / 4, T), T, 0, s2>>>(W_e, pWe, 600, 1800, KP18);
    cudaEventRecord(evW, s2);                   // Wh + We converts done -> E/F

    // ---- s1: Wh1 -> A (split-A, no pack) -> We1 -> B ----
    cvt_f32_b16<<<cdiv(2048 * 4096 / 4, T), T, 0, s1>>>(W_h1, pWh1, 2048 * 4096, 0);
    gemm256<<<16 * 8, 256, GSMEM, s1>>>(A_);
    cvt_f32_b16<<<cdiv(600 * 2048 / 4, T), T, 0, s1>>>(W_e1, pWe1, 600 * 2048, 0);
    gemm128<<<16 * 5, 256, GSMEM, s1>>>(B_);
    cudaEventRecord(evB, s1);

    // ---- s0: D -> E -> F -> score ----
    cudaStreamWaitEvent(s0, evD, 0);            // C_Q on s0 order; C_rest+We2 via evD
    gemm128<<<8 * 5, 256, GSMEM, s0>>>(D_);
    cudaStreamWaitEvent(s0, evB, 0);
    cudaStreamWaitEvent(s0, evW, 0);
    gemm128<<<8 * 15, 256, GSMEM, s0>>>(E_);
    gemm128<<<8 * 5, 256, GSMEM, s0>>>(F_);
    score_kernel<<<BATCH, 256, 0, s0>>>(L, pls, nls, out);
}

// round 17
// speedup vs baseline: 1.1118x; 1.1118x over previous
#include <cuda_runtime.h>
#include <cuda_bf16.h>
#include <mma.h>
#include <cstdint>

using namespace nvcuda;

#if defined(__CUDA_ARCH_SPECIFIC__) || defined(__CUDA_ARCH_FEAT_SM103_ALL) || defined(__CUDA_ARCH_FEAT_SM100_ALL)
#define HAS_TCGEN05 1
#else
#define HAS_TCGEN05 0
#endif

// ---------------------------------------------------------------------------
#define BATCH   1024
#define NNEG    128
#define ED      600
#define VFS_D   12288
#define OBJ_VD  4096

#define KP18    1920            // 1800 padded to 128-multiple
#define NP600   768
#define NP1800  2048

// ---------------------------------------------------------------------------
__device__ __nv_bfloat16 g_Rv [BATCH * VFS_D];
__device__ __nv_bfloat16 g_X12[2048 * 4096];
__device__ __nv_bfloat16 g_Wh1[2048 * 4096];
__device__ __nv_bfloat16 g_We1[NP600 * 2048];
__device__ __nv_bfloat16 g_Wh2[4096 * 12288];
__device__ __nv_bfloat16 g_We2[NP600 * 4096];
__device__ __nv_bfloat16 g_Wh [NP1800 * KP18];
__device__ __nv_bfloat16 g_We [NP600 * KP18];
__device__ __nv_bfloat16 g_H1 [2048 * 2048];
__device__ __nv_bfloat16 g_H2 [1024 * 4096];
__device__ __nv_bfloat16 g_Z  [1024 * KP18];
__device__ __nv_bfloat16 g_H  [1024 * KP18];
__device__ float         g_emb[1024 * ED];

// ---------------------------------------------------------------------------
__device__ __forceinline__ uint32_t sptr(const void* p) {
    return (uint32_t)__cvta_generic_to_shared(p);
}
__device__ __forceinline__ void cp16(uint32_t s, const void* g) {
    asm volatile("cp.async.cg.shared.global [%0], [%1], 16;" :: "r"(s), "l"(g));
}
__device__ __forceinline__ void cp_commit() {
    asm volatile("cp.async.commit_group;");
}
template<int N> __device__ __forceinline__ void cp_wait() {
    asm volatile("cp.async.wait_group %0;" :: "n"(N));
}

struct GD {
    const __nv_bfloat16 *A, *W;
    const float *bias;
    __nv_bfloat16 *out1, *out2;
    float *outF;
    int lda, ldw, N, K, ldc, split, relu, nbx;
};

#if HAS_TCGEN05
__device__ __forceinline__ uint32_t elect1() {
    uint32_t r;
    asm volatile("{\n\t.reg .pred p;\n\telect.sync _|p, 0xFFFFFFFF;\n\t"
                 "selp.b32 %0, 1, 0, p;\n\t}" : "=r"(r));
    return r;
}

#define TCGEN05_ALLOC(saddr, ncols) \
    asm volatile("tcgen05.alloc.cta_group::1.sync.aligned.shared::cta.b32 [%0], %1;" \
                 :: "r"((uint32_t)(saddr)), "r"((uint32_t)(ncols)) : "memory")
#define TCGEN05_DEALLOC(tmem, ncols) \
    asm volatile("tcgen05.dealloc.cta_group::1.sync.aligned.b32 %0, %1;" \
                 :: "r"(tmem), "r"((uint32_t)(ncols)))
#define TCGEN05_RELINQUISH() \
    asm volatile("tcgen05.relinquish_alloc_permit.cta_group::1.sync.aligned;")
#define TCGEN05_COMMIT(mbar) \
    asm volatile("tcgen05.commit.cta_group::1.mbarrier::arrive::one.shared::cluster.b64 [%0];" \
                 :: "r"((uint32_t)(mbar)) : "memory")
#define TCGEN05_FENCE_AFTER() \
    asm volatile("tcgen05.fence::after_thread_sync;" ::: "memory")
#define TCGEN05_FENCE_BEFORE() \
    asm volatile("tcgen05.fence::before_thread_sync;" ::: "memory")
#define TCGEN05_WAIT_LD() \
    asm volatile("tcgen05.wait::ld.sync.aligned;" ::: "memory")
#define FENCE_PROXY_ASYNC() \
    asm volatile("fence.proxy.async.shared::cta;" ::: "memory")
#define MBARRIER_INIT(mbar, cnt) \
    asm volatile("mbarrier.init.shared.b64 [%0], %1;" \
                 :: "r"((uint32_t)(mbar)), "r"((uint32_t)(cnt)) : "memory")

#define MBARRIER_WAIT_PARITY(mbar_smem_addr, phase_parity) do { \
    uint32_t _mbar = (uint32_t)(mbar_smem_addr); \
    uint32_t _parity = (uint32_t)(phase_parity); \
    uint32_t _done; \
    asm volatile( \
        "{\n\t.reg .pred p;\n\t" \
        "mbarrier.try_wait.parity.acquire.cta.shared::cta.b64 p, [%1], %2;\n\t" \
        "selp.b32 %0, 1, 0, p;\n\t}" \
        : "=r"(_done) : "r"(_mbar), "r"(_parity) : "memory"); \
    if (!_done) { \
        asm volatile( \
            "{\n\t.reg .pred P1;\n\t" \
            "WAIT_LOOP_%=:\n\t" \
            "mbarrier.try_wait.parity.acquire.cta.shared::cta.b64 P1, [%0], %1, 0x989680;\n\t" \
            "@P1 bra.uni WAIT_DONE_%=;\n\t" \
            "bra.uni WAIT_LOOP_%=;\n\t" \
            "WAIT_DONE_%=:\n\t}" \
            :: "r"(_mbar), "r"(_parity) : "memory"); \
    } \
} while(0)

#define TCGEN05_LD_32X32B_X32(r, tmem_addr) \
    asm volatile( \
        "tcgen05.ld.sync.aligned.32x32b.x32.b32 " \
        "{%0, %1, %2, %3, %4, %5, %6, %7, " \
        " %8, %9, %10, %11, %12, %13, %14, %15, " \
        " %16, %17, %18, %19, %20, %21, %22, %23, " \
        " %24, %25, %26, %27, %28, %29, %30, %31}, [%32];" \
        : "=r"((r)[0]),  "=r"((r)[1]),  "=r"((r)[2]),  "=r"((r)[3]), \
          "=r"((r)[4]),  "=r"((r)[5]),  "=r"((r)[6]),  "=r"((r)[7]), \
          "=r"((r)[8]),  "=r"((r)[9]),  "=r"((r)[10]), "=r"((r)[11]), \
          "=r"((r)[12]), "=r"((r)[13]), "=r"((r)[14]), "=r"((r)[15]), \
          "=r"((r)[16]), "=r"((r)[17]), "=r"((r)[18]), "=r"((r)[19]), \
          "=r"((r)[20]), "=r"((r)[21]), "=r"((r)[22]), "=r"((r)[23]), \
          "=r"((r)[24]), "=r"((r)[25]), "=r"((r)[26]), "=r"((r)[27]), \
          "=r"((r)[28]), "=r"((r)[29]), "=r"((r)[30]), "=r"((r)[31]) \
        : "r"(tmem_addr))

// SW128 K-major smem descriptor
static constexpr uint64_t DESC_BASE =
    (uint64_t(2) << 61) | (uint64_t(1) << 46) | (uint64_t(64) << 32) | (uint64_t(1) << 16);

// idescs: kind::f16, dtype=F32, atype=btype=BF16, M=128
#define IDESC128 ((1u << 4) | (1u << 7) | (1u << 10) | ((128u / 8) << 17) | ((128u / 16) << 24))
#define IDESC256 ((1u << 4) | (1u << 7) | (1u << 10) | ((256u / 8) << 17) | ((128u / 16) << 24))

__device__ __forceinline__ void mma_bf16_ss(uint32_t d, uint64_t ad, uint64_t bd,
                                            uint32_t idesc, uint32_t enable) {
    asm volatile(
        "{\n\t.reg .pred p;\n\tsetp.ne.u32 p, %5, 0;\n\t"
        "tcgen05.mma.cta_group::1.kind::f16 [%0], %1, %2, %3, {%4,%4,%4,%4}, p;\n\t}"
        :: "r"(d), "l"(ad), "l"(bd), "r"(idesc), "r"(0u), "r"(enable) : "memory");
}
#endif  // HAS_TCGEN05

// ---------------------------------------------------------------------------
// Converts / pack
// ---------------------------------------------------------------------------
static inline int cdiv(int a, int b) { return (a + b - 1) / b; }

__global__ void cvt_f32_b16(const float* __restrict__ src, __nv_bfloat16* __restrict__ dst,
                            int n, int do_relu) {
    int i = (blockIdx.x * blockDim.x + threadIdx.x) * 4;
    if (i >= n) return;
    float4 v = *reinterpret_cast<const float4*>(src + i);
    if (do_relu) {
        v.x = fmaxf(v.x, 0.f); v.y = fmaxf(v.y, 0.f);
        v.z = fmaxf(v.z, 0.f); v.w = fmaxf(v.w, 0.f);
    }
    *reinterpret_cast<__nv_bfloat162*>(dst + i)     = __floats2bfloat162_rn(v.x, v.y);
    *reinterpret_cast<__nv_bfloat162*>(dst + i + 2) = __floats2bfloat162_rn(v.z, v.w);
}

__global__ void cvt2d_f32_b16(const float* __restrict__ src, __nv_bfloat16* __restrict__ dst,
                              int R, int Ks, int Kd) {
    int i = (blockIdx.x * blockDim.x + threadIdx.x) * 4;
    if (i >= R * Ks) return;
    int r = i / Ks, c = i - r * Ks;
    float4 v = *reinterpret_cast<const float4*>(src + i);
    __nv_bfloat16* d = dst + (size_t)r * Kd + c;
    *reinterpret_cast<__nv_bfloat162*>(d)     = __floats2bfloat162_rn(v.x, v.y);
    *reinterpret_cast<__nv_bfloat162*>(d + 2) = __floats2bfloat162_rn(v.z, v.w);
}

__global__ void pack_x12() {
    const int vecs = 2048 * 4096 / 8;
    int i = blockIdx.x * blockDim.x + threadIdx.x;
    if (i >= vecs) return;
    int e = i * 8;
    int m = e >> 12;
    int k = e & 4095;
    int src = (m & 1023) * VFS_D + ((m < 1024) ? 0 : (VFS_D - OBJ_VD)) + k;
    *reinterpret_cast<uint4*>(g_X12 + e) = *reinterpret_cast<const uint4*>(g_Rv + src);
}

// ---------------------------------------------------------------------------
// Shared wmma fallback tile (plain sm_103 pass only; not selected on 103a)
// ---------------------------------------------------------------------------
#if !HAS_TCGEN05
#define LDSB 72
__device__ void wmma_tile128(const GD& d, int m0, int n0, char* smraw,
                             int tid, int warp, int lane) {
    __nv_bfloat16* Asm = reinterpret_cast<__nv_bfloat16*>(smraw);
    __nv_bfloat16* Bsm = Asm + 2 * 128 * LDSB;
    const int wm = warp >> 2;
    const int wn = warp & 3;

    wmma::fragment<wmma::accumulator, 16, 16, 16, float> acc[4][2];
#pragma unroll
    for (int i = 0; i < 4; i++)
#pragma unroll
        for (int j = 0; j < 2; j++)
            wmma::fill_fragment(acc[i][j], 0.0f);

    const int KT = d.K >> 6;
    auto issue = [&](int kt) {
        const int k0 = kt << 6;
        __nv_bfloat16* a = Asm + (kt & 1) * 128 * LDSB;
        __nv_bfloat16* b = Bsm + (kt & 1) * 128 * LDSB;
#pragma unroll
        for (int t = 0; t < 4; t++) {
            int v = tid + t * 256;
            int r = v >> 3;
            int c = (v & 7) << 3;
            cp16(sptr(a + r * LDSB + c), d.A + (size_t)(m0 + r) * d.lda + k0 + c);
            cp16(sptr(b + r * LDSB + c), d.W + (size_t)(n0 + r) * d.ldw + k0 + c);
        }
        cp_commit();
    };

    issue(0);
    for (int kt = 0; kt < KT; kt++) {
        if (kt + 1 < KT) { issue(kt + 1); cp_wait<1>(); }
        else             { cp_wait<0>(); }
        __syncthreads();
        const __nv_bfloat16* a = Asm + (kt & 1) * 128 * LDSB;
        const __nv_bfloat16* b = Bsm + (kt & 1) * 128 * LDSB;
#pragma unroll
        for (int kk = 0; kk < 64; kk += 16) {
            wmma::fragment<wmma::matrix_a, 16, 16, 16, __nv_bfloat16, wmma::row_major> af[4];
            wmma::fragment<wmma::matrix_b, 16, 16, 16, __nv_bfloat16, wmma::col_major> bf[2];
#pragma unroll
            for (int i = 0; i < 4; i++)
                wmma::load_matrix_sync(af[i], a + (wm * 64 + i * 16) * LDSB + kk, LDSB);
#pragma unroll
            for (int j = 0; j < 2; j++)
                wmma::load_matrix_sync(bf[j], b + (wn * 32 + j * 16) * LDSB + kk, LDSB);
#pragma unroll
            for (int i = 0; i < 4; i++)
#pragma unroll
                for (int j = 0; j < 2; j++)
                    wmma::mma_sync(acc[i][j], af[i], bf[j], acc[i][j]);
        }
        __syncthreads();
    }

    float* st = reinterpret_cast<float*>(smraw) + warp * 256;
#pragma unroll
    for (int i = 0; i < 4; i++) {
#pragma unroll
        for (int j = 0; j < 2; j++) {
            wmma::store_matrix_sync(st, acc[i][j], 16, wmma::mem_row_major);
            __syncwarp();
            int m_base = m0 + wm * 64 + i * 16;
            int n_base = n0 + wn * 32 + j * 16;
#pragma unroll
            for (int e = 0; e < 8; e++) {
                int idx = lane * 8 + e;
                int r = idx >> 4, c = idx & 15;
                int gm = m_base + r;
                int gn = n_base + c;
                if (gn < d.N) {
                    float vv = st[idx] + d.bias[gn];
                    if (d.relu) vv = fmaxf(vv, 0.f);
                    if (d.outF) {
                        d.outF[(size_t)gm * d.ldc + gn] = vv;
                    } else {
                        __nv_bfloat16 hv = __float2bfloat16(vv);
                        if (gm < d.split) d.out1[(size_t)gm * d.ldc + gn] = hv;
                        else              d.out2[(size_t)(gm - d.split) * d.ldc + gn] = hv;
                    }
                }
            }
            __syncwarp();
        }
    }
    __syncthreads();
}
#endif

// ---------------------------------------------------------------------------
// GEMM kernel 1: 128(M) x 128(N) tile, K-chunk 128, 3-stage
// GEMM kernel 2: 128(M) x 256(N) tile, K-chunk 64, 4-stage
// ---------------------------------------------------------------------------
#define STG128_BYTES 65536
#define AB128        32768
#define ASTG256      16384
#define STG256_BYTES 49152
#define GSMEM        200704     // 4096 (align+control) + 196608

__global__ __launch_bounds__(256)
void gemm128(GD d) {
    const int bx = blockIdx.x;
    const int m0 = (bx / d.nbx) * 128;
    const int n0 = (bx % d.nbx) * 128;
    const int tid  = threadIdx.x;
    const int warp = tid >> 5;
    const int lane = tid & 31;

#if HAS_TCGEN05
    extern __shared__ char smraw[];
    const uint32_t sm0   = sptr(smraw);
    const uint32_t mbar0 = sm0 + 8;
    float* biasS = reinterpret_cast<float*>(smraw + 64);
    const uint32_t sA0   = (sm0 + 4095u) & ~4095u;

    const int KT = d.K >> 7;

    if (warp == 0) TCGEN05_ALLOC(sm0, 128);
    if (tid < 3) MBARRIER_INIT(mbar0 + tid * 8, 1);
    if (tid >= 64 && tid < 192) {
        int c = tid - 64;
        biasS[c] = (n0 + c < d.N) ? d.bias[n0 + c] : 0.f;
    }
    __syncthreads();

    uint32_t tmem;
    asm volatile("ld.shared.b32 %0, [%1];" : "=r"(tmem) : "r"(sm0));

    auto issue = [&](int kt, int buf) {
        const uint32_t aS = sA0 + buf * STG128_BYTES;
        const uint32_t bS = aS + AB128;
        const int k0 = kt << 7;
#pragma unroll
        for (int i = 0; i < 8; i++) {
            int v = tid + i * 256;
            int r = v >> 4;
            int c = v & 15;
            uint32_t off = ((uint32_t)(r >> 3) << 10) + ((uint32_t)(c >> 3) << 14)
                         + ((uint32_t)(r & 7) << 7) + ((uint32_t)(c & 7) << 4);
            off ^= (off >> 3) & 0x70u;
            cp16(aS + off, d.A + (size_t)(m0 + r) * d.lda + k0 + (c << 3));
            cp16(bS + off, d.W + (size_t)(n0 + r) * d.ldw + k0 + (c << 3));
        }
        cp_commit();
    };

    issue(0, 0); issue(1, 1); issue(2, 2);

    for (int kt = 0; kt < KT; kt++) {
        const int buf = kt % 3;
        const int rem = KT - kt - 1;
        if (rem >= 2)      cp_wait<2>();
        else if (rem == 1) cp_wait<1>();
        else               cp_wait<0>();
        FENCE_PROXY_ASYNC();
        __syncthreads();

        if (warp == 0 && elect1()) {
            const uint32_t aS = sA0 + buf * STG128_BYTES;
            const uint64_t ad = DESC_BASE | ((aS >> 4) & 0x3FFF);
            const uint64_t bd = DESC_BASE | (((aS + AB128) >> 4) & 0x3FFF);
#pragma unroll
            for (int j = 0; j < 8; j++) {
                uint64_t off = (j < 4) ? (uint64_t)(2 * j) : (uint64_t)(1024 + 2 * (j - 4));
                mma_bf16_ss(tmem, ad + off, bd + off, IDESC128,
                            (kt > 0 || j > 0) ? 1u : 0u);
            }
            TCGEN05_COMMIT(mbar0 + buf * 8);
        }

        if (kt + 3 < KT) {
            MBARRIER_WAIT_PARITY(mbar0 + buf * 8, (uint32_t)((kt / 3) & 1));
            issue(kt + 3, buf);
        }
    }

    {
        const int lb = (KT - 1) % 3;
        MBARRIER_WAIT_PARITY(mbar0 + lb * 8, (uint32_t)(((KT - 1) / 3) & 1));
    }
    TCGEN05_FENCE_AFTER();

    if (warp < 4) {
        const int gm = m0 + warp * 32 + lane;
#pragma unroll
        for (int ch = 0; ch < 4; ch++) {
            uint32_t r[32];
            TCGEN05_LD_32X32B_X32(r, tmem + ch * 32);
            TCGEN05_WAIT_LD();
            const int nb = n0 + ch * 32;
            if (d.outF) {
                float* po = d.outF + (size_t)gm * d.ldc;
#pragma unroll
                for (int c = 0; c < 32; c++) {
                    int gn = nb + c;
                    if (gn < d.N) {
                        float v = __uint_as_float(r[c]) + biasS[ch * 32 + c];
                        if (d.relu) v = fmaxf(v, 0.f);
                        po[gn] = v;
                    }
                }
            } else {
                __nv_bfloat16* po = (gm < d.split) ? d.out1 + (size_t)gm * d.ldc
                                                   : d.out2 + (size_t)(gm - d.split) * d.ldc;
#pragma unroll
                for (int p = 0; p < 16; p++) {
                    int gn = nb + 2 * p;
                    if (gn < d.N) {
                        float v0 = __uint_as_float(r[2 * p])     + biasS[ch * 32 + 2 * p];
                        float v1 = __uint_as_float(r[2 * p + 1]) + biasS[ch * 32 + 2 * p + 1];
                        if (d.relu) { v0 = fmaxf(v0, 0.f); v1 = fmaxf(v1, 0.f); }
                        uint32_t pk;
                        asm("cvt.rn.bf16x2.f32 %0, %1, %2;" : "=r"(pk) : "f"(v1), "f"(v0));
                        *reinterpret_cast<uint32_t*>(po + gn) = pk;
                    }
                }
            }
        }
        TCGEN05_FENCE_BEFORE();
    }
    __syncthreads();
    if (warp == 0) {
        TCGEN05_RELINQUISH();
        TCGEN05_DEALLOC(tmem, 128);
    }
#else
    extern __shared__ char smraw[];
    wmma_tile128(d, m0, n0, smraw, tid, warp, lane);
#endif
}

__global__ __launch_bounds__(256)
void gemm256(GD d) {
    const int bx = blockIdx.x;
    const int m0 = (bx / d.nbx) * 128;
    const int n0 = (bx % d.nbx) * 256;
    const int tid  = threadIdx.x;
    const int warp = tid >> 5;
    const int lane = tid & 31;

#if HAS_TCGEN05
    extern __shared__ char smraw[];
    const uint32_t sm0   = sptr(smraw);
    const uint32_t mbar0 = sm0 + 8;
    float* biasS = reinterpret_cast<float*>(smraw + 64);
    const uint32_t sA0   = (sm0 + 4095u) & ~4095u;

    const int KT = d.K >> 6;

    if (warp == 0) TCGEN05_ALLOC(sm0, 256);
    if (tid < 4) MBARRIER_INIT(mbar0 + tid * 8, 1);
    biasS[tid] = (n0 + tid < d.N) ? d.bias[n0 + tid] : 0.f;
    __syncthreads();

    uint32_t tmem;
    asm volatile("ld.shared.b32 %0, [%1];" : "=r"(tmem) : "r"(sm0));

    auto issue = [&](int kt, int buf) {
        const uint32_t base = sA0 + buf * STG256_BYTES;
        const int k0 = kt << 6;
#pragma unroll
        for (int i = 0; i < 4; i++) {
            int v = tid + i * 256;
            int r = v >> 3;
            int c = v & 7;
            uint32_t off = ((uint32_t)r << 7) + ((uint32_t)c << 4);
            off ^= (off >> 3) & 0x70u;
            cp16(base + off, d.A + (size_t)(m0 + r) * d.lda + k0 + (c << 3));
        }
#pragma unroll
        for (int i = 0; i < 8; i++) {
            int v = tid + i * 256;
            int r = v >> 3;
            int c = v & 7;
            uint32_t off = ((uint32_t)r << 7) + ((uint32_t)c << 4);
            off ^= (off >> 3) & 0x70u;
            cp16(base + ASTG256 + off, d.W + (size_t)(n0 + r) * d.ldw + k0 + (c << 3));
        }
        cp_commit();
    };

    issue(0, 0); issue(1, 1); issue(2, 2); issue(3, 3);

    for (int kt = 0; kt < KT; kt++) {
        const int buf = kt & 3;
        const int rem = KT - kt - 1;
        if (rem >= 3)      cp_wait<3>();
        else if (rem == 2) cp_wait<2>();
        else if (rem == 1) cp_wait<1>();
        else               cp_wait<0>();
        FENCE_PROXY_ASYNC();
        __syncthreads();

        if (warp == 0 && elect1()) {
            const uint32_t base = sA0 + buf * STG256_BYTES;
            const uint64_t ad = DESC_BASE | ((base >> 4) & 0x3FFF);
            const uint64_t bd = DESC_BASE | (((base + ASTG256) >> 4) & 0x3FFF);
#pragma unroll
            for (int k = 0; k < 4; k++) {
                mma_bf16_ss(tmem, ad + 2 * k, bd + 2 * k, IDESC256,
                            (kt > 0 || k > 0) ? 1u : 0u);
            }
            TCGEN05_COMMIT(mbar0 + buf * 8);
        }

        if (kt + 4 < KT) {
            MBARRIER_WAIT_PARITY(mbar0 + buf * 8, (uint32_t)((kt >> 2) & 1));
            issue(kt + 4, buf);
        }
    }

    {
        const int lb = (KT - 1) & 3;
        MBARRIER_WAIT_PARITY(mbar0 + lb * 8, (uint32_t)(((KT - 1) >> 2) & 1));
    }
    TCGEN05_FENCE_AFTER();

    {
        const int h  = warp >> 2;
        const int w4 = warp & 3;
        const int gm = m0 + w4 * 32 + lane;
#pragma unroll
        for (int ch = 0; ch < 4; ch++) {
            uint32_t r[32];
            const int colbase = h * 128 + ch * 32;
            TCGEN05_LD_32X32B_X32(r, tmem + colbase);
            TCGEN05_WAIT_LD();
            const int nb = n0 + colbase;
            if (d.outF) {
                float* po = d.outF + (size_t)gm * d.ldc;
#pragma unroll
                for (int c = 0; c < 32; c++) {
                    int gn = nb + c;
                    if (gn < d.N) {
                        float v = __uint_as_float(r[c]) + biasS[colbase + c];
                        if (d.relu) v = fmaxf(v, 0.f);
                        po[gn] = v;
                    }
                }
            } else {
                __nv_bfloat16* po = (gm < d.split) ? d.out1 + (size_t)gm * d.ldc
                                                   : d.out2 + (size_t)(gm - d.split) * d.ldc;
#pragma unroll
                for (int p = 0; p < 16; p++) {
                    int gn = nb + 2 * p;
                    if (gn < d.N) {
                        float v0 = __uint_as_float(r[2 * p])     + biasS[colbase + 2 * p];
                        float v1 = __uint_as_float(r[2 * p + 1]) + biasS[colbase + 2 * p + 1];
                        if (d.relu) { v0 = fmaxf(v0, 0.f); v1 = fmaxf(v1, 0.f); }
                        uint32_t pk;
                        asm("cvt.rn.bf16x2.f32 %0, %1, %2;" : "=r"(pk) : "f"(v1), "f"(v0));
                        *reinterpret_cast<uint32_t*>(po + gn) = pk;
                    }
                }
            }
        }
        TCGEN05_FENCE_BEFORE();
    }
    __syncthreads();
    if (warp == 0) {
        TCGEN05_RELINQUISH();
        TCGEN05_DEALLOC(tmem, 256);
    }
#else
    extern __shared__ char smraw[];
    wmma_tile128(d, m0, n0, smraw, tid, warp, lane);
    wmma_tile128(d, m0, n0 + 128, smraw, tid, warp, lane);
#endif
}

// ---------------------------------------------------------------------------
// Scoring
// ---------------------------------------------------------------------------
__global__ void score_kernel(const float* __restrict__ L,
                             const int* __restrict__ pls,
                             const int* __restrict__ nls,
                             float* __restrict__ out) {
    int b = blockIdx.x;
    __shared__ float es[ED];
    for (int i = threadIdx.x; i < ED; i += blockDim.x) es[i] = g_emb[b * ED + i];
    __syncthreads();

    int warp = threadIdx.x >> 5;
    int lane = threadIdx.x & 31;
    for (int j = warp; j < NNEG + 1; j += 8) {
        int idx = (j == 0) ? pls[b] : nls[b * NNEG + (j - 1)];
        const float* Lr = L + (size_t)idx * ED;
        float s = 0.f;
        for (int c = lane; c < ED; c += 32) {
            float d = fmaxf(Lr[c] - es[c], 0.f);
            s += d * d;
        }
#pragma unroll
        for (int o = 16; o; o >>= 1) s += __shfl_xor_sync(0xffffffffu, s, o);
        if (lane == 0) out[b * (NNEG + 1) + j] = -sqrtf(s);
    }
}

// ---------------------------------------------------------------------------
// Launch: R15 schedule (validated 360.5us) + single change: GEMM D gates on
// evD (recorded after We2 cvt) instead of evW, so D overlaps Wh/We converts.
// All event records precede their waits in host issue order (capture-safe).
// ---------------------------------------------------------------------------
extern "C" void kernel_launch(void* const* d_in, const int* in_sizes, int n_in,
                              void* d_out, int out_size) {
    const float* vfs  = (const float*)d_in[0];
    const float* L    = (const float*)d_in[1];
    const int*   pls  = (const int*)  d_in[2];
    const int*   nls  = (const int*)  d_in[3];
    const float* W_h1 = (const float*)d_in[4];
    const float* b_h1 = (const float*)d_in[5];
    const float* W_e1 = (const float*)d_in[6];
    const float* b_e1 = (const float*)d_in[7];
    const float* W_h2 = (const float*)d_in[8];
    const float* b_h2 = (const float*)d_in[9];
    const float* W_e2 = (const float*)d_in[10];
    const float* b_e2 = (const float*)d_in[11];
    const float* W_h  = (const float*)d_in[12];
    const float* b_h  = (const float*)d_in[13];
    const float* W_e  = (const float*)d_in[14];
    const float* b_e  = (const float*)d_in[15];
    float* out = (float*)d_out;

    __nv_bfloat16 *pRv, *pX12, *pWh1, *pWe1, *pWh2, *pWe2, *pWh, *pWe;
    __nv_bfloat16 *pH1, *pH2, *pZ, *pH;
    float *pEmb;
    cudaGetSymbolAddress((void**)&pRv,  g_Rv);
    cudaGetSymbolAddress((void**)&pX12, g_X12);
    cudaGetSymbolAddress((void**)&pWh1, g_Wh1);
    cudaGetSymbolAddress((void**)&pWe1, g_We1);
    cudaGetSymbolAddress((void**)&pWh2, g_Wh2);
    cudaGetSymbolAddress((void**)&pWe2, g_We2);
    cudaGetSymbolAddress((void**)&pWh,  g_Wh);
    cudaGetSymbolAddress((void**)&pWe,  g_We);
    cudaGetSymbolAddress((void**)&pH1,  g_H1);
    cudaGetSymbolAddress((void**)&pH2,  g_H2);
    cudaGetSymbolAddress((void**)&pZ,   g_Z);
    cudaGetSymbolAddress((void**)&pH,   g_H);
    cudaGetSymbolAddress((void**)&pEmb, g_emb);

    cudaFuncSetAttribute(gemm128, cudaFuncAttributeMaxDynamicSharedMemorySize, GSMEM);
    cudaFuncSetAttribute(gemm256, cudaFuncAttributeMaxDynamicSharedMemorySize, GSMEM);

    static cudaStream_t s1 = nullptr, s2 = nullptr;
    static cudaEvent_t evFork = nullptr, evRv = nullptr, evB = nullptr,
                       evW = nullptr, evWh2a = nullptr, evD = nullptr;
    if (!s1) {
        cudaStreamCreateWithFlags(&s1, cudaStreamNonBlocking);
        cudaStreamCreateWithFlags(&s2, cudaStreamNonBlocking);
        cudaEventCreateWithFlags(&evFork,  cudaEventDisableTiming);
        cudaEventCreateWithFlags(&evRv,    cudaEventDisableTiming);
        cudaEventCreateWithFlags(&evB,     cudaEventDisableTiming);
        cudaEventCreateWithFlags(&evW,     cudaEventDisableTiming);
        cudaEventCreateWithFlags(&evWh2a,  cudaEventDisableTiming);
        cudaEventCreateWithFlags(&evD,     cudaEventDisableTiming);
    }
    cudaStream_t s0 = 0;

    const int T = 256;
    const size_t WH2_HALF = (size_t)2048 * VFS_D;   // elements in half of Wh2

    // ---- s0: pad memsets, then fork ----
    cudaMemsetAsync(pWe1 + 600 * 2048, 0, (size_t)(NP600 - 600) * 2048 * 2, s0);
    cudaMemsetAsync(pWe2 + 600 * 4096, 0, (size_t)(NP600 - 600) * 4096 * 2, s0);
    cudaMemsetAsync(pWh,  0, (size_t)NP1800 * KP18 * 2, s0);
    cudaMemsetAsync(pWe,  0, (size_t)NP600 * KP18 * 2, s0);
    cudaMemsetAsync(pZ,   0, (size_t)1024 * KP18 * 2, s0);
    cudaMemsetAsync(pH,   0, (size_t)1024 * KP18 * 2, s0);
    cudaEventRecord(evFork, s0);
    cudaStreamWaitEvent(s1, evFork, 0);
    cudaStreamWaitEvent(s2, evFork, 0);

    // GEMM descriptors
    GD A_  = { pX12, pWh1, b_h1, pH1, pH1, nullptr, 4096, 4096, 2048, 4096, 2048, 2048, 1, 8 };
    GD C1_ = { pRv, pWh2,            b_h2,        pH2,        pH2,        nullptr,
               VFS_D, VFS_D, 2048, VFS_D, 4096, 1024, 1, 8 };
    GD C2_ = { pRv, pWh2 + WH2_HALF, b_h2 + 2048, pH2 + 2048, pH2 + 2048, nullptr,
               VFS_D, VFS_D, 2048, VFS_D, 4096, 1024, 1, 8 };
    GD B_  = { pH1, pWe1, b_e1, pZ, pZ + 1200, nullptr, 2048, 2048, 600, 2048, KP18, 1024, 1, 5 };
    GD D_  = { pH2, pWe2, b_e2, pZ + 600, pZ + 600, nullptr, 4096, 4096, 600, 4096, KP18, 1024, 1, 5 };
    GD E_  = { pZ, pWh, b_h, pH, pH, nullptr, KP18, KP18, 1800, KP18, KP18, 1024, 1, 15 };
    GD F_  = { pH, pWe, b_e, nullptr, nullptr, pEmb, KP18, KP18, 600, KP18, ED, 1024, 0, 5 };

    // ---- s1 first: cvt Rv, record evRv ----
    cvt_f32_b16<<<cdiv(BATCH * VFS_D / 4, T), T, 0, s1>>>(vfs, pRv, BATCH * VFS_D, 1);
    cudaEventRecord(evRv, s1);

    // ---- s0 (critical path): cvt Wh2 half1 -> wait Rv -> GEMM C1 ----
    cvt_f32_b16<<<cdiv((int)(WH2_HALF / 4), T), T, 0, s0>>>(W_h2, pWh2, (int)WH2_HALF, 0);
    cudaEventRecord(evWh2a, s0);
    cudaStreamWaitEvent(s0, evRv, 0);
    gemm256<<<8 * 8, 256, GSMEM, s0>>>(C1_);   // 64 CTAs

    // ---- s2: cvt Wh2 half2 (overlaps C1) -> GEMM C2 -> We2 (evD) -> Wh/We (evW) ----
    cudaStreamWaitEvent(s2, evWh2a, 0);
    cvt_f32_b16<<<cdiv((int)(WH2_HALF / 4), T), T, 0, s2>>>(
        W_h2 + WH2_HALF, pWh2 + WH2_HALF, (int)WH2_HALF, 0);
    cudaStreamWaitEvent(s2, evRv, 0);
    gemm256<<<8 * 8, 256, GSMEM, s2>>>(C2_);   // 64 CTAs, dovetails with C1
    cvt_f32_b16<<<cdiv(600 * 4096 / 4, T), T, 0, s2>>>(W_e2, pWe2, 600 * 4096, 0);
    cudaEventRecord(evD, s2);                  // C2 + We2 done -> D can run
    cvt2d_f32_b16<<<cdiv(1800 * 1800 / 4, T), T, 0, s2>>>(W_h, pWh, 1800, 1800, KP18);
    cvt2d_f32_b16<<<cdiv(600 * 1800 / 4, T), T, 0, s2>>>(W_e, pWe, 600, 1800, KP18);
    cudaEventRecord(evW, s2);                  // Wh + We converts done -> E/F

    // ---- s1: Wh1 -> pack -> A -> We1 -> B ----
    cvt_f32_b16<<<cdiv(2048 * 4096 / 4, T), T, 0, s1>>>(W_h1, pWh1, 2048 * 4096, 0);
    pack_x12<<<cdiv(2048 * 4096 / 8, T), T, 0, s1>>>();
    gemm256<<<16 * 8, 256, GSMEM, s1>>>(A_);
    cvt_f32_b16<<<cdiv(600 * 2048 / 4, T), T, 0, s1>>>(W_e1, pWe1, 600 * 2048, 0);
    gemm128<<<16 * 5, 256, GSMEM, s1>>>(B_);
    cudaEventRecord(evB, s1);

    // ---- s0: D -> E -> F -> score ----
    cudaStreamWaitEvent(s0, evD, 0);   // C1 in s0 order; C2 + We2 via evD
    gemm128<<<8 * 5, 256, GSMEM, s0>>>(D_);
    cudaStreamWaitEvent(s0, evB, 0);
    cudaStreamWaitEvent(s0, evW, 0);
    gemm128<<<8 * 15, 256, GSMEM, s0>>>(E_);
    gemm128<<<8 * 5, 256, GSMEM, s0>>>(F_);
    score_kernel<<<BATCH, 256, 0, s0>>>(L, pls, nls, out);
}